// round 6
// baseline (speedup 1.0000x reference)
#include <cuda_runtime.h>
#include <math.h>

// ---------------------------------------------------------------------------
// One-pass fused: tile pipeline runs with m=0, inv=1 (mean/std cancel for
// full-count windows); each block emits sum/sumsq partials for its disjoint
// tile.  The block drawing the LAST ticket combines partials (MLP-4) and
// recomputes out[0:376) and out[n-376:n) exactly (mean/inv, true counts).
// 256-thread blocks (4/SM), merged-barrier scans.
// ---------------------------------------------------------------------------

#define THREADS 256
#define NW      (THREADS / 32)        // 8 warps
#define CHUNK   16
#define L       4096                  // floats per block
#define NV4     1024                  // float4 per region
#define HALO    384
#define TILE    (L - 2 * HALO)        // 3328 outputs per block
#define R1      125
#define R2      250
#define INV_KA  (1.0f / 251.0f)
#define INV_KV  (1.0f / 501.0f)
#define FIXW    376

#define SWZ(u) ((u) ^ (((u) >> 3) & 7))   // 16B-unit swizzle

#define MAXB 8192
__device__ double   g_psum[MAXB];
__device__ double   g_psq[MAXB];
__device__ unsigned g_ticket = 0;

// ---------------------------------------------------------------------------
__global__ __launch_bounds__(THREADS, 4)
void main_kernel(const float* __restrict__ x, float* __restrict__ out,
                 int n, int nb) {
    __shared__ float4 A[NV4];          // chunk-local prefix of x / (x-m)
    __shared__ float4 B[NV4];          // chunk-local prefix of w^2 / z^2-1
    __shared__ float  vexA[THREADS], vexB[THREADS];
    __shared__ float  wsA[NW], wsB[NW];
    __shared__ float  sred[NW], qred[NW];
    __shared__ double ds[NW], dq[NW];
    __shared__ float  sh_mean, sh_inv;
    __shared__ unsigned sh_ticket;

    int t = threadIdx.x;
    int lane = t & 31, w = t >> 5;
    int base = (int)blockIdx.x * TILE - HALO;
    bool interior = (base >= 0) && (base + L <= n);

    // ================= tile pipeline (m=0, inv=1) =================
    {
        float p[CHUNK];
        int g0 = base + t * CHUNK;
        if (interior) {
            const float4* xv = (const float4*)(x + g0);
#pragma unroll
            for (int r = 0; r < 4; r++) {
                float4 a = xv[r];
                p[4*r+0] = a.x; p[4*r+1] = a.y; p[4*r+2] = a.z; p[4*r+3] = a.w;
            }
        } else {
#pragma unroll
            for (int k = 0; k < CHUNK; k++) {
                int g = g0 + k;
                p[k] = (g >= 0 && g < n) ? x[g] : 0.f;
            }
        }

        // per-block sum/sumsq partial over the tile region
        {
            float s = 0.f, q = 0.f;
            if (t >= HALO / CHUNK && t < (HALO + TILE) / CHUNK) {
#pragma unroll
                for (int k = 0; k < CHUNK; k++) { s += p[k]; q = fmaf(p[k], p[k], q); }
            }
#pragma unroll
            for (int o = 16; o > 0; o >>= 1) {
                s += __shfl_down_sync(0xffffffffu, s, o);
                q += __shfl_down_sync(0xffffffffu, q, o);
            }
            if (lane == 0) { sred[w] = s; qred[w] = q; }
        }

        // chunk prefix + vec4 store into A
#pragma unroll
        for (int k = 1; k < CHUNK; k++) p[k] += p[k-1];
        {
            int ub = 4 * t;
            A[SWZ(ub+0)] = make_float4(p[0],  p[1],  p[2],  p[3]);
            A[SWZ(ub+1)] = make_float4(p[4],  p[5],  p[6],  p[7]);
            A[SWZ(ub+2)] = make_float4(p[8],  p[9],  p[10], p[11]);
            A[SWZ(ub+3)] = make_float4(p[12], p[13], p[14], p[15]);
        }

        // scan of chunk totals
        {
            float tot = p[15], v = tot;
#pragma unroll
            for (int o = 1; o < 32; o <<= 1) {
                float y = __shfl_up_sync(0xffffffffu, v, o);
                if (lane >= o) v += y;
            }
            vexA[t] = v - tot;
            if (lane == 31) wsA[w] = v;
            __syncthreads();
            if (t < NW) {
                float wv = wsA[t];
#pragma unroll
                for (int o = 1; o < NW; o <<= 1) {
                    float y = __shfl_up_sync((1u << NW) - 1u, wv, o, NW);
                    if (t >= o) wv += y;
                }
                wsA[t] = wv;
            }
            if (t == 32) {
                double S = 0.0, Q = 0.0;
#pragma unroll
                for (int k = 0; k < NW; k++) { S += (double)sred[k]; Q += (double)qred[k]; }
                g_psum[blockIdx.x] = S;
                g_psq[blockIdx.x]  = Q;
            }
            __syncthreads();
        }

        // w = x - W251(x)/251 into p[], prefix of w^2 into B
        {
            float fh[20], fl[20];
            int bh = 4 * t + 31;
            int bl = 4 * t - 32;
#pragma unroll
            for (int i = 0; i < 5; i++) {
                int ih = bh + i; if (ih > NV4 - 1) ih = NV4 - 1;
                float4 vh = A[SWZ(ih)];
                fh[4*i+0]=vh.x; fh[4*i+1]=vh.y; fh[4*i+2]=vh.z; fh[4*i+3]=vh.w;
                int il = bl + i; if (il < 0) il = 0;
                float4 vl = A[SWZ(il)];
                fl[4*i+0]=vl.x; fl[4*i+1]=vl.y; fl[4*i+2]=vl.z; fl[4*i+3]=vl.w;
            }
            int ih0 = (t + 7 < THREADS) ? t + 7 : THREADS - 1;
            int ih1 = (t + 8 < THREADS) ? t + 8 : THREADS - 1;
            int il0 = (t - 8 >= 0) ? t - 8 : 0;
            int il1 = (t - 7 >= 0) ? t - 7 : 0;
            float oh0 = vexA[ih0] + ((ih0 >> 5) ? wsA[(ih0 >> 5) - 1] : 0.f);
            float oh1 = vexA[ih1] + ((ih1 >> 5) ? wsA[(ih1 >> 5) - 1] : 0.f);
            float ol0 = vexA[il0] + ((il0 >> 5) ? wsA[(il0 >> 5) - 1] : 0.f);
            float ol1 = vexA[il1] + ((il1 >> 5) ? wsA[(il1 >> 5) - 1] : 0.f);

#pragma unroll
            for (int k = CHUNK - 1; k >= 1; k--) p[k] -= p[k-1];

            bool safe = (t >= 8) && (t < 248) && interior;
            float vp = 0.f, vb4[4];
#pragma unroll
            for (int k = 0; k < CHUNK; k++) {
                float Ph = fh[k + 1] + (k < 3  ? oh0 : oh1);
                float Pl = fl[k + 2] + (k < 14 ? ol0 : ol1);
                float z  = p[k] - (Ph - Pl) * INV_KA;
                float vv;
                if (safe) {
                    vv = z * z;
                } else {
                    int j = t * CHUNK + k, g = base + j;
                    bool valid = (j >= R1 + 1) && (j < L - R1 - 1) &&
                                 (g >= 0) && (g < n);
                    vv = valid ? z * z : 0.f;
                }
                vp += vv;
                p[k] = z;
                vb4[k & 3] = vp;
                if ((k & 3) == 3)
                    B[SWZ(4*t + (k >> 2))] = make_float4(vb4[0], vb4[1], vb4[2], vb4[3]);
            }

            float tot = vp, v = tot;
#pragma unroll
            for (int o = 1; o < 32; o <<= 1) {
                float y = __shfl_up_sync(0xffffffffu, v, o);
                if (lane >= o) v += y;
            }
            vexB[t] = v - tot;
            if (lane == 31) wsB[w] = v;
            __syncthreads();
            if (t < NW) {
                float wv = wsB[t];
#pragma unroll
                for (int o = 1; o < NW; o <<= 1) {
                    float y = __shfl_up_sync((1u << NW) - 1u, wv, o, NW);
                    if (t >= o) wv += y;
                }
                wsB[t] = wv;
            }
            __syncthreads();
        }

        // outputs (strip region skipped; finisher writes it)
        if (t >= HALO / CHUNK && t < (HALO + TILE) / CHUNK) {
            float gh[20], gl[20];
            int bh = 4 * t + 62;
            int bl = 4 * t - 63;
#pragma unroll
            for (int i = 0; i < 5; i++) {
                float4 vh = B[SWZ(bh + i)];
                gh[4*i+0]=vh.x; gh[4*i+1]=vh.y; gh[4*i+2]=vh.z; gh[4*i+3]=vh.w;
                float4 vl = B[SWZ(bl + i)];
                gl[4*i+0]=vl.x; gl[4*i+1]=vl.y; gl[4*i+2]=vl.z; gl[4*i+3]=vl.w;
            }
            int jh0 = t + 15, jh1 = t + 16, jl0 = t - 16, jl1 = t - 15;
            float ozh0 = vexB[jh0] + ((jh0 >> 5) ? wsB[(jh0 >> 5) - 1] : 0.f);
            float ozh1 = vexB[jh1] + ((jh1 >> 5) ? wsB[(jh1 >> 5) - 1] : 0.f);
            float ozl0 = vexB[jl0] + ((jl0 >> 5) ? wsB[(jl0 >> 5) - 1] : 0.f);
            float ozl1 = vexB[jl1] + ((jl1 >> 5) ? wsB[(jl1 >> 5) - 1] : 0.f);

            if (interior) {
                float4* ov = (float4*)(out + base + t * CHUNK);
                float r4[4];
#pragma unroll
                for (int k = 0; k < CHUNK; k++) {
                    float Wh = gh[k + 2] + (k < 6  ? ozh0 : ozh1);
                    float Wl = gl[k + 1] + (k < 11 ? ozl0 : ozl1);
                    float mv = fmaxf((Wh - Wl) * INV_KV, 1e-30f);
                    float rs;
                    asm("rsqrt.approx.f32 %0, %1;" : "=f"(rs) : "f"(mv));
                    r4[k & 3] = p[k] * rs;
                    if ((k & 3) == 3)
                        __stcs(&ov[k >> 2], make_float4(r4[0], r4[1], r4[2], r4[3]));
                }
            } else {
#pragma unroll
                for (int k = 0; k < CHUNK; k++) {
                    int g = base + t * CHUNK + k;
                    if (g >= FIXW && g < n - FIXW) {
                        float Wh = gh[k + 2] + (k < 6  ? ozh0 : ozh1);
                        float Wl = gl[k + 1] + (k < 11 ? ozl0 : ozl1);
                        float mv = fmaxf((Wh - Wl) * INV_KV, 1e-30f);
                        float rs;
                        asm("rsqrt.approx.f32 %0, %1;" : "=f"(rs) : "f"(mv));
                        out[g] = p[k] * rs;
                    }
                }
            }
        }
    }

    // ================= ticket: last block finishes =================
    __threadfence();
    __syncthreads();
    if (t == 0) sh_ticket = atomicAdd(&g_ticket, 1u);
    __syncthreads();
    if (sh_ticket != (unsigned)(nb - 1)) return;

    // ---- combine partials (MLP-4) ----
    {
        double S0 = 0.0, S1 = 0.0, S2 = 0.0, S3 = 0.0;
        double Q0 = 0.0, Q1 = 0.0, Q2 = 0.0, Q3 = 0.0;
        int k = t;
        for (; k + 3 * THREADS < nb; k += 4 * THREADS) {
            S0 += g_psum[k];               Q0 += g_psq[k];
            S1 += g_psum[k + THREADS];     Q1 += g_psq[k + THREADS];
            S2 += g_psum[k + 2 * THREADS]; Q2 += g_psq[k + 2 * THREADS];
            S3 += g_psum[k + 3 * THREADS]; Q3 += g_psq[k + 3 * THREADS];
        }
        for (; k < nb; k += THREADS) { S0 += g_psum[k]; Q0 += g_psq[k]; }
        double S = (S0 + S1) + (S2 + S3);
        double Q = (Q0 + Q1) + (Q2 + Q3);
#pragma unroll
        for (int o = 16; o > 0; o >>= 1) {
            S += __shfl_down_sync(0xffffffffu, S, o);
            Q += __shfl_down_sync(0xffffffffu, Q, o);
        }
        if (lane == 0) { ds[w] = S; dq[w] = Q; }
        __syncthreads();
        if (t == 0) {
            double S2d = 0.0, Q2d = 0.0;
#pragma unroll
            for (int j = 0; j < NW; j++) { S2d += ds[j]; Q2d += dq[j]; }
            double mean = S2d / (double)n;
            double var  = (Q2d - (double)n * mean * mean) / ((double)n - 1.0);
            if (var < 0.0) var = 0.0;
            sh_mean = (float)mean;
            sh_inv  = (float)(1.0 / (sqrt(var) + 1e-5));
            g_ticket = 0;                    // reset for graph replay
        }
        __syncthreads();
    }
    float mean = sh_mean, inv = sh_inv;

    // ---- exact strip recompute: s=0 head, s=1 tail ----
    for (int s = 0; s < 2; s++) {
        int fb = (s == 0) ? -HALO : (n - TILE - HALO);
        __syncthreads();                      // protect shared reuse

        float p[CHUNK];
        int g0 = fb + t * CHUNK;
#pragma unroll
        for (int k = 0; k < CHUNK; k++) {
            int g = g0 + k;
            p[k] = (g >= 0 && g < n) ? (x[g] - mean) : 0.f;
        }
#pragma unroll
        for (int k = 1; k < CHUNK; k++) p[k] += p[k-1];
        {
            int ub = 4 * t;
            A[SWZ(ub+0)] = make_float4(p[0],  p[1],  p[2],  p[3]);
            A[SWZ(ub+1)] = make_float4(p[4],  p[5],  p[6],  p[7]);
            A[SWZ(ub+2)] = make_float4(p[8],  p[9],  p[10], p[11]);
            A[SWZ(ub+3)] = make_float4(p[12], p[13], p[14], p[15]);
        }
        {
            float tot = p[15], v = tot;
#pragma unroll
            for (int o = 1; o < 32; o <<= 1) {
                float y = __shfl_up_sync(0xffffffffu, v, o);
                if (lane >= o) v += y;
            }
            vexA[t] = v - tot;
            if (lane == 31) wsA[w] = v;
            __syncthreads();
            if (t < NW) {
                float wv = wsA[t];
#pragma unroll
                for (int o = 1; o < NW; o <<= 1) {
                    float y = __shfl_up_sync((1u << NW) - 1u, wv, o, NW);
                    if (t >= o) wv += y;
                }
                wsA[t] = wv;
            }
            __syncthreads();
        }
        {
            float fh[20], fl[20];
            int bh = 4 * t + 31, bl = 4 * t - 32;
#pragma unroll
            for (int i = 0; i < 5; i++) {
                int ih = bh + i; if (ih > NV4 - 1) ih = NV4 - 1;
                float4 vh = A[SWZ(ih)];
                fh[4*i+0]=vh.x; fh[4*i+1]=vh.y; fh[4*i+2]=vh.z; fh[4*i+3]=vh.w;
                int il = bl + i; if (il < 0) il = 0;
                float4 vl = A[SWZ(il)];
                fl[4*i+0]=vl.x; fl[4*i+1]=vl.y; fl[4*i+2]=vl.z; fl[4*i+3]=vl.w;
            }
            int ih0 = (t + 7 < THREADS) ? t + 7 : THREADS - 1;
            int ih1 = (t + 8 < THREADS) ? t + 8 : THREADS - 1;
            int il0 = (t - 8 >= 0) ? t - 8 : 0;
            int il1 = (t - 7 >= 0) ? t - 7 : 0;
            float oh0 = vexA[ih0] + ((ih0 >> 5) ? wsA[(ih0 >> 5) - 1] : 0.f);
            float oh1 = vexA[ih1] + ((ih1 >> 5) ? wsA[(ih1 >> 5) - 1] : 0.f);
            float ol0 = vexA[il0] + ((il0 >> 5) ? wsA[(il0 >> 5) - 1] : 0.f);
            float ol1 = vexA[il1] + ((il1 >> 5) ? wsA[(il1 >> 5) - 1] : 0.f);
#pragma unroll
            for (int k = CHUNK - 1; k >= 1; k--) p[k] -= p[k-1];

            float vp = 0.f, vb4[4];
#pragma unroll
            for (int k = 0; k < CHUNK; k++) {
                int j = t * CHUNK + k, g = fb + j;
                float Ph = fh[k + 1] + (k < 3  ? oh0 : oh1);
                float Pl = fl[k + 2] + (k < 14 ? ol0 : ol1);
                float z  = inv * (p[k] - (Ph - Pl) * INV_KA);
                bool valid = (j >= R1 + 1) && (j < L - R1 - 1) &&
                             (g >= 0) && (g < n);
                float vv = valid ? fmaf(z, z, -1.f) : 0.f;
                vp += vv;
                p[k] = z;
                vb4[k & 3] = vp;
                if ((k & 3) == 3)
                    B[SWZ(4*t + (k >> 2))] = make_float4(vb4[0], vb4[1], vb4[2], vb4[3]);
            }
            float tot = vp, v = tot;
#pragma unroll
            for (int o = 1; o < 32; o <<= 1) {
                float y = __shfl_up_sync(0xffffffffu, v, o);
                if (lane >= o) v += y;
            }
            vexB[t] = v - tot;
            if (lane == 31) wsB[w] = v;
            __syncthreads();
            if (t < NW) {
                float wv = wsB[t];
#pragma unroll
                for (int o = 1; o < NW; o <<= 1) {
                    float y = __shfl_up_sync((1u << NW) - 1u, wv, o, NW);
                    if (t >= o) wv += y;
                }
                wsB[t] = wv;
            }
            __syncthreads();
        }
        if (t >= HALO / CHUNK && t < (HALO + TILE) / CHUNK) {
            float gh[20], gl[20];
            int bh = 4 * t + 62, bl = 4 * t - 63;
#pragma unroll
            for (int i = 0; i < 5; i++) {
                float4 vh = B[SWZ(bh + i)];
                gh[4*i+0]=vh.x; gh[4*i+1]=vh.y; gh[4*i+2]=vh.z; gh[4*i+3]=vh.w;
                float4 vl = B[SWZ(bl + i)];
                gl[4*i+0]=vl.x; gl[4*i+1]=vl.y; gl[4*i+2]=vl.z; gl[4*i+3]=vl.w;
            }
            int jh0 = t + 15, jh1 = t + 16, jl0 = t - 16, jl1 = t - 15;
            float ozh0 = vexB[jh0] + ((jh0 >> 5) ? wsB[(jh0 >> 5) - 1] : 0.f);
            float ozh1 = vexB[jh1] + ((jh1 >> 5) ? wsB[(jh1 >> 5) - 1] : 0.f);
            float ozl0 = vexB[jl0] + ((jl0 >> 5) ? wsB[(jl0 >> 5) - 1] : 0.f);
            float ozl1 = vexB[jl1] + ((jl1 >> 5) ? wsB[(jl1 >> 5) - 1] : 0.f);
#pragma unroll
            for (int k = 0; k < CHUNK; k++) {
                int g = fb + t * CHUNK + k;
                if (g >= 0 && g < n && (g < FIXW || g >= n - FIXW)) {
                    float Wh = gh[k + 2] + (k < 6  ? ozh0 : ozh1);
                    float Wl = gl[k + 1] + (k < 11 ? ozl0 : ozl1);
                    int lo = g - R2; if (lo < 0) lo = 0;
                    int hi = g + R2; if (hi > n - 1) hi = n - 1;
                    float cnt = (float)(hi - lo + 1);
                    float mv = fmaxf((Wh - Wl + cnt) * INV_KV, 1e-30f);
                    float rs;
                    asm("rsqrt.approx.f32 %0, %1;" : "=f"(rs) : "f"(mv));
                    out[g] = p[k] * rs;
                }
            }
        }
    }
}

// ---------------------------------------------------------------------------
extern "C" void kernel_launch(void* const* d_in, const int* in_sizes, int n_in,
                              void* d_out, int out_size) {
    const float* x = (const float*)d_in[0];
    int n = in_sizes[0];
    float* out = (float*)d_out;

    int blocks = (n + TILE - 1) / TILE;
    main_kernel<<<blocks, THREADS>>>(x, out, n, blocks);

    if (out_size > n && n_in > 1) {
        cudaMemcpyAsync(out + n, d_in[1],
                        (size_t)(out_size - n) * sizeof(float),
                        cudaMemcpyDeviceToDevice);
    }
}

// round 7
// speedup vs baseline: 1.2061x; 1.2061x over previous
#include <cuda_runtime.h>
#include <math.h>

// ---------------------------------------------------------------------------
// Two-kernel: main runs with m=0, inv=1 (mean/std cancel for full-count
// windows) and emits per-block sum/sumsq partials; fix_kernel (2 blocks)
// combines partials (MLP-4) and recomputes out[0:376) / out[n-376:n) exactly.
// Main: 256-thread blocks (4/SM), merged-barrier scans, window loops split
// into 8-element halves to stay under the 64-register cap (no spills).
// ---------------------------------------------------------------------------

#define THREADS 256
#define NW      (THREADS / 32)        // 8 warps
#define CHUNK   16
#define L       4096
#define NV4     1024
#define HALO    384
#define TILE    (L - 2 * HALO)        // 3328 outputs per block
#define R1      125
#define R2      250
#define INV_KA  (1.0f / 251.0f)
#define INV_KV  (1.0f / 501.0f)
#define FIXW    376

#define SWZ(u) ((u) ^ (((u) >> 3) & 7))   // 16B-unit swizzle

#define MAXB 8192
__device__ double g_psum[MAXB];
__device__ double g_psq[MAXB];

// ---------------------------------------------------------------------------
__global__ __launch_bounds__(THREADS, 4)
void main_kernel(const float* __restrict__ x, float* __restrict__ out, int n) {
    __shared__ float4 A[NV4];
    __shared__ float4 B[NV4];
    __shared__ float  vexA[THREADS], vexB[THREADS];
    __shared__ float  wsA[NW], wsB[NW];
    __shared__ float  sred[NW], qred[NW];

    int t = threadIdx.x;
    int lane = t & 31, w = t >> 5;
    int base = (int)blockIdx.x * TILE - HALO;
    bool interior = (base >= 0) && (base + L <= n);

    // ---- load own chunk ----
    float p[CHUNK];
    int g0 = base + t * CHUNK;
    if (interior) {
        const float4* xv = (const float4*)(x + g0);
#pragma unroll
        for (int r = 0; r < 4; r++) {
            float4 a = xv[r];
            p[4*r+0] = a.x; p[4*r+1] = a.y; p[4*r+2] = a.z; p[4*r+3] = a.w;
        }
    } else {
#pragma unroll
        for (int k = 0; k < CHUNK; k++) {
            int g = g0 + k;
            p[k] = (g >= 0 && g < n) ? x[g] : 0.f;
        }
    }

    // ---- per-block sum/sumsq over tile region ----
    {
        float s = 0.f, q = 0.f;
        if (t >= HALO / CHUNK && t < (HALO + TILE) / CHUNK) {
#pragma unroll
            for (int k = 0; k < CHUNK; k++) { s += p[k]; q = fmaf(p[k], p[k], q); }
        }
#pragma unroll
        for (int o = 16; o > 0; o >>= 1) {
            s += __shfl_down_sync(0xffffffffu, s, o);
            q += __shfl_down_sync(0xffffffffu, q, o);
        }
        if (lane == 0) { sred[w] = s; qred[w] = q; }
    }

    // ---- chunk prefix + store into A ----
#pragma unroll
    for (int k = 1; k < CHUNK; k++) p[k] += p[k-1];
    {
        int ub = 4 * t;
        A[SWZ(ub+0)] = make_float4(p[0],  p[1],  p[2],  p[3]);
        A[SWZ(ub+1)] = make_float4(p[4],  p[5],  p[6],  p[7]);
        A[SWZ(ub+2)] = make_float4(p[8],  p[9],  p[10], p[11]);
        A[SWZ(ub+3)] = make_float4(p[12], p[13], p[14], p[15]);
    }

    // ---- scan of chunk totals ----
    {
        float tot = p[15], v = tot;
#pragma unroll
        for (int o = 1; o < 32; o <<= 1) {
            float y = __shfl_up_sync(0xffffffffu, v, o);
            if (lane >= o) v += y;
        }
        vexA[t] = v - tot;
        if (lane == 31) wsA[w] = v;
        __syncthreads();
        if (t < NW) {
            float wv = wsA[t];
#pragma unroll
            for (int o = 1; o < NW; o <<= 1) {
                float y = __shfl_up_sync((1u << NW) - 1u, wv, o, NW);
                if (t >= o) wv += y;
            }
            wsA[t] = wv;
        }
        if (t == 32) {
            double S = 0.0, Q = 0.0;
#pragma unroll
            for (int k = 0; k < NW; k++) { S += (double)sred[k]; Q += (double)qred[k]; }
            g_psum[blockIdx.x] = S;
            g_psq[blockIdx.x]  = Q;
        }
        __syncthreads();
    }

    // ---- phase 3 (two 8-element halves): w into p[], prefix w^2 into B ----
    {
        int ih0 = (t + 7 < THREADS) ? t + 7 : THREADS - 1;
        int ih1 = (t + 8 < THREADS) ? t + 8 : THREADS - 1;
        int il0 = (t - 8 >= 0) ? t - 8 : 0;
        int il1 = (t - 7 >= 0) ? t - 7 : 0;
        float oh0 = vexA[ih0] + ((ih0 >> 5) ? wsA[(ih0 >> 5) - 1] : 0.f);
        float oh1 = vexA[ih1] + ((ih1 >> 5) ? wsA[(ih1 >> 5) - 1] : 0.f);
        float ol0 = vexA[il0] + ((il0 >> 5) ? wsA[(il0 >> 5) - 1] : 0.f);
        float ol1 = vexA[il1] + ((il1 >> 5) ? wsA[(il1 >> 5) - 1] : 0.f);

#pragma unroll
        for (int k = CHUNK - 1; k >= 1; k--) p[k] -= p[k-1];

        bool safe = (t >= 8) && (t < 248) && interior;
        float vp = 0.f, vb4[4];
#pragma unroll
        for (int h = 0; h < 2; h++) {
            float fh[12], fl[12];
            int bh = 4 * t + 31 + 2 * h;
            int bl = 4 * t - 32 + 2 * h;
#pragma unroll
            for (int i = 0; i < 3; i++) {
                int ih = bh + i; if (ih > NV4 - 1) ih = NV4 - 1;
                float4 vh = A[SWZ(ih)];
                fh[4*i+0]=vh.x; fh[4*i+1]=vh.y; fh[4*i+2]=vh.z; fh[4*i+3]=vh.w;
                int il = bl + i; if (il < 0) il = 0;
                float4 vl = A[SWZ(il)];
                fl[4*i+0]=vl.x; fl[4*i+1]=vl.y; fl[4*i+2]=vl.z; fl[4*i+3]=vl.w;
            }
#pragma unroll
            for (int kk = 0; kk < 8; kk++) {
                int k = h * 8 + kk;
                float Ph = fh[kk + 1] + ((h == 0 && kk < 3) ? oh0 : oh1);
                float Pl = fl[kk + 2] + ((h == 0 || kk < 6) ? ol0 : ol1);
                float z  = p[k] - (Ph - Pl) * INV_KA;
                float vv;
                if (safe) {
                    vv = z * z;
                } else {
                    int j = t * CHUNK + k, g = base + j;
                    bool valid = (j >= R1 + 1) && (j < L - R1 - 1) &&
                                 (g >= 0) && (g < n);
                    vv = valid ? z * z : 0.f;
                }
                vp += vv;
                p[k] = z;
                vb4[k & 3] = vp;
                if ((k & 3) == 3)
                    B[SWZ(4*t + (k >> 2))] = make_float4(vb4[0], vb4[1], vb4[2], vb4[3]);
            }
        }

        float tot = vp, v = tot;
#pragma unroll
        for (int o = 1; o < 32; o <<= 1) {
            float y = __shfl_up_sync(0xffffffffu, v, o);
            if (lane >= o) v += y;
        }
        vexB[t] = v - tot;
        if (lane == 31) wsB[w] = v;
        __syncthreads();
        if (t < NW) {
            float wv = wsB[t];
#pragma unroll
            for (int o = 1; o < NW; o <<= 1) {
                float y = __shfl_up_sync((1u << NW) - 1u, wv, o, NW);
                if (t >= o) wv += y;
            }
            wsB[t] = wv;
        }
        __syncthreads();
    }

    // ---- phase 5 (two halves): outputs ----
    if (t >= HALO / CHUNK && t < (HALO + TILE) / CHUNK) {   // [24,232)
        int jh0 = t + 15, jh1 = t + 16, jl0 = t - 16, jl1 = t - 15;
        float ozh0 = vexB[jh0] + ((jh0 >> 5) ? wsB[(jh0 >> 5) - 1] : 0.f);
        float ozh1 = vexB[jh1] + ((jh1 >> 5) ? wsB[(jh1 >> 5) - 1] : 0.f);
        float ozl0 = vexB[jl0] + ((jl0 >> 5) ? wsB[(jl0 >> 5) - 1] : 0.f);
        float ozl1 = vexB[jl1] + ((jl1 >> 5) ? wsB[(jl1 >> 5) - 1] : 0.f);

        float4* ov = (float4*)(out + base + t * CHUNK);
        float r4[4];
#pragma unroll
        for (int h = 0; h < 2; h++) {
            float gh[12], gl[12];
            int bh = 4 * t + 62 + 2 * h;
            int bl = 4 * t - 63 + 2 * h;
#pragma unroll
            for (int i = 0; i < 3; i++) {
                float4 vh = B[SWZ(bh + i)];
                gh[4*i+0]=vh.x; gh[4*i+1]=vh.y; gh[4*i+2]=vh.z; gh[4*i+3]=vh.w;
                float4 vl = B[SWZ(bl + i)];
                gl[4*i+0]=vl.x; gl[4*i+1]=vl.y; gl[4*i+2]=vl.z; gl[4*i+3]=vl.w;
            }
            if (interior) {
#pragma unroll
                for (int kk = 0; kk < 8; kk++) {
                    int k = h * 8 + kk;
                    float Wh = gh[kk + 2] + ((h == 0 && kk < 6) ? ozh0 : ozh1);
                    float Wl = gl[kk + 1] + ((h == 0 || kk < 3) ? ozl0 : ozl1);
                    float mv = fmaxf((Wh - Wl) * INV_KV, 1e-30f);
                    float rs;
                    asm("rsqrt.approx.f32 %0, %1;" : "=f"(rs) : "f"(mv));
                    r4[k & 3] = p[k] * rs;
                    if ((k & 3) == 3)
                        __stcs(&ov[k >> 2], make_float4(r4[0], r4[1], r4[2], r4[3]));
                }
            } else {
#pragma unroll
                for (int kk = 0; kk < 8; kk++) {
                    int k = h * 8 + kk;
                    int g = base + t * CHUNK + k;
                    if (g >= FIXW && g < n - FIXW) {
                        float Wh = gh[kk + 2] + ((h == 0 && kk < 6) ? ozh0 : ozh1);
                        float Wl = gl[kk + 1] + ((h == 0 || kk < 3) ? ozl0 : ozl1);
                        float mv = fmaxf((Wh - Wl) * INV_KV, 1e-30f);
                        float rs;
                        asm("rsqrt.approx.f32 %0, %1;" : "=f"(rs) : "f"(mv));
                        out[g] = p[k] * rs;
                    }
                }
            }
        }
    }
}

// ---------------------------------------------------------------------------
// Boundary fixup: L=2048, CHUNK=8.  Combines partials with 4-way MLP, then
// recomputes the head/tail strips exactly (mean/inv, true counts).
#define FL     2048
#define FNV4   512
#define FCHUNK 8
#define FTILE  (FL - 2 * HALO)        // 1280

__global__ __launch_bounds__(THREADS, 4)
void fix_kernel(const float* __restrict__ x, float* __restrict__ out,
                int n, int nb) {
    __shared__ float4 A[FNV4];
    __shared__ float4 B[FNV4];
    __shared__ float  vexA[THREADS], vexB[THREADS];
    __shared__ float  wsA[NW], wsB[NW];
    __shared__ double ds[NW], dq[NW];
    __shared__ float  sh_mean, sh_inv;

    int t = threadIdx.x;
    int lane = t & 31, w = t >> 5;

    // ---- combine partials (MLP-4) ----
    {
        double S0 = 0.0, S1 = 0.0, S2 = 0.0, S3 = 0.0;
        double Q0 = 0.0, Q1 = 0.0, Q2 = 0.0, Q3 = 0.0;
        int k = t;
        for (; k + 3 * THREADS < nb; k += 4 * THREADS) {
            S0 += g_psum[k];               Q0 += g_psq[k];
            S1 += g_psum[k + THREADS];     Q1 += g_psq[k + THREADS];
            S2 += g_psum[k + 2 * THREADS]; Q2 += g_psq[k + 2 * THREADS];
            S3 += g_psum[k + 3 * THREADS]; Q3 += g_psq[k + 3 * THREADS];
        }
        for (; k < nb; k += THREADS) { S0 += g_psum[k]; Q0 += g_psq[k]; }
        double S = (S0 + S1) + (S2 + S3);
        double Q = (Q0 + Q1) + (Q2 + Q3);
#pragma unroll
        for (int o = 16; o > 0; o >>= 1) {
            S += __shfl_down_sync(0xffffffffu, S, o);
            Q += __shfl_down_sync(0xffffffffu, Q, o);
        }
        if (lane == 0) { ds[w] = S; dq[w] = Q; }
        __syncthreads();
        if (t == 0) {
            double S2d = 0.0, Q2d = 0.0;
#pragma unroll
            for (int j = 0; j < NW; j++) { S2d += ds[j]; Q2d += dq[j]; }
            double mean = S2d / (double)n;
            double var  = (Q2d - (double)n * mean * mean) / ((double)n - 1.0);
            if (var < 0.0) var = 0.0;
            sh_mean = (float)mean;
            sh_inv  = (float)(1.0 / (sqrt(var) + 1e-5));
        }
        __syncthreads();
    }
    float mean = sh_mean, inv = sh_inv;

    int base = (blockIdx.x == 0) ? -HALO : (n - FL + HALO);  // outputs cover strip

    // ---- load chunk of 8, u = x - mean ----
    float p[FCHUNK];
    int g0 = base + t * FCHUNK;
#pragma unroll
    for (int k = 0; k < FCHUNK; k++) {
        int g = g0 + k;
        p[k] = (g >= 0 && g < n) ? (x[g] - mean) : 0.f;
    }
#pragma unroll
    for (int k = 1; k < FCHUNK; k++) p[k] += p[k-1];
    {
        int ub = 2 * t;
        A[SWZ(ub+0)] = make_float4(p[0], p[1], p[2], p[3]);
        A[SWZ(ub+1)] = make_float4(p[4], p[5], p[6], p[7]);
    }
    {
        float tot = p[7], v = tot;
#pragma unroll
        for (int o = 1; o < 32; o <<= 1) {
            float y = __shfl_up_sync(0xffffffffu, v, o);
            if (lane >= o) v += y;
        }
        vexA[t] = v - tot;
        if (lane == 31) wsA[w] = v;
        __syncthreads();
        if (t < NW) {
            float wv = wsA[t];
#pragma unroll
            for (int o = 1; o < NW; o <<= 1) {
                float y = __shfl_up_sync((1u << NW) - 1u, wv, o, NW);
                if (t >= o) wv += y;
            }
            wsA[t] = wv;
        }
        __syncthreads();
    }
    // ---- z, prefix of z^2-1 into B ----
    {
        float fh[12], fl[12];
        int bh = 2 * t + 31;
        int bl = 2 * t - 32;
#pragma unroll
        for (int i = 0; i < 3; i++) {
            int ih = bh + i; if (ih > FNV4 - 1) ih = FNV4 - 1;
            float4 vh = A[SWZ(ih)];
            fh[4*i+0]=vh.x; fh[4*i+1]=vh.y; fh[4*i+2]=vh.z; fh[4*i+3]=vh.w;
            int il = bl + i; if (il < 0) il = 0;
            float4 vl = A[SWZ(il)];
            fl[4*i+0]=vl.x; fl[4*i+1]=vl.y; fl[4*i+2]=vl.z; fl[4*i+3]=vl.w;
        }
        int ih0 = (t + 15 < THREADS) ? t + 15 : THREADS - 1;
        int ih1 = (t + 16 < THREADS) ? t + 16 : THREADS - 1;
        int il0 = (t - 16 >= 0) ? t - 16 : 0;
        int il1 = (t - 15 >= 0) ? t - 15 : 0;
        float oh0 = vexA[ih0] + ((ih0 >> 5) ? wsA[(ih0 >> 5) - 1] : 0.f);
        float oh1 = vexA[ih1] + ((ih1 >> 5) ? wsA[(ih1 >> 5) - 1] : 0.f);
        float ol0 = vexA[il0] + ((il0 >> 5) ? wsA[(il0 >> 5) - 1] : 0.f);
        float ol1 = vexA[il1] + ((il1 >> 5) ? wsA[(il1 >> 5) - 1] : 0.f);
#pragma unroll
        for (int k = FCHUNK - 1; k >= 1; k--) p[k] -= p[k-1];

        float vp = 0.f, vb4[4];
#pragma unroll
        for (int k = 0; k < FCHUNK; k++) {
            int j = t * FCHUNK + k, g = base + j;
            float Ph = fh[k + 1] + (k < 3 ? oh0 : oh1);   // P[j+125]
            float Pl = fl[k + 2] + (k < 6 ? ol0 : ol1);   // P[j-126]
            float z  = inv * (p[k] - (Ph - Pl) * INV_KA);
            bool valid = (j >= R1 + 1) && (j < FL - R1 - 1) &&
                         (g >= 0) && (g < n);
            float vv = valid ? fmaf(z, z, -1.f) : 0.f;
            vp += vv;
            p[k] = z;
            vb4[k & 3] = vp;
            if ((k & 3) == 3)
                B[SWZ(2*t + (k >> 2))] = make_float4(vb4[0], vb4[1], vb4[2], vb4[3]);
        }
        float tot = vp, v = tot;
#pragma unroll
        for (int o = 1; o < 32; o <<= 1) {
            float y = __shfl_up_sync(0xffffffffu, v, o);
            if (lane >= o) v += y;
        }
        vexB[t] = v - tot;
        if (lane == 31) wsB[w] = v;
        __syncthreads();
        if (t < NW) {
            float wv = wsB[t];
#pragma unroll
            for (int o = 1; o < NW; o <<= 1) {
                float y = __shfl_up_sync((1u << NW) - 1u, wv, o, NW);
                if (t >= o) wv += y;
            }
            wsB[t] = wv;
        }
        __syncthreads();
    }
    // ---- outputs: strip only ----
    if (t >= HALO / FCHUNK && t < (HALO + FTILE) / FCHUNK) {   // [48,208)
        float gh[12], gl[12];
        int bh = 2 * t + 62;
        int bl = 2 * t - 63;
#pragma unroll
        for (int i = 0; i < 3; i++) {
            float4 vh = B[SWZ(bh + i)];
            gh[4*i+0]=vh.x; gh[4*i+1]=vh.y; gh[4*i+2]=vh.z; gh[4*i+3]=vh.w;
            float4 vl = B[SWZ(bl + i)];
            gl[4*i+0]=vl.x; gl[4*i+1]=vl.y; gl[4*i+2]=vl.z; gl[4*i+3]=vl.w;
        }
        int jh0 = t + 31, jh1 = t + 32, jl0 = t - 32, jl1 = t - 31;
        float ozh0 = vexB[jh0] + ((jh0 >> 5) ? wsB[(jh0 >> 5) - 1] : 0.f);
        float ozh1 = vexB[jh1] + ((jh1 >> 5) ? wsB[(jh1 >> 5) - 1] : 0.f);
        float ozl0 = vexB[jl0] + ((jl0 >> 5) ? wsB[(jl0 >> 5) - 1] : 0.f);
        float ozl1 = vexB[jl1] + ((jl1 >> 5) ? wsB[(jl1 >> 5) - 1] : 0.f);
#pragma unroll
        for (int k = 0; k < FCHUNK; k++) {
            int g = base + t * FCHUNK + k;
            if (g >= 0 && g < n && (g < FIXW || g >= n - FIXW)) {
                float Wh = gh[k + 2] + (k < 6 ? ozh0 : ozh1);  // P2[j+250]
                float Wl = gl[k + 1] + (k < 3 ? ozl0 : ozl1);  // P2[j-251]
                int lo = g - R2; if (lo < 0) lo = 0;
                int hi = g + R2; if (hi > n - 1) hi = n - 1;
                float cnt = (float)(hi - lo + 1);
                float mv = fmaxf((Wh - Wl + cnt) * INV_KV, 1e-30f);
                float rs;
                asm("rsqrt.approx.f32 %0, %1;" : "=f"(rs) : "f"(mv));
                out[g] = p[k] * rs;
            }
        }
    }
}

// ---------------------------------------------------------------------------
extern "C" void kernel_launch(void* const* d_in, const int* in_sizes, int n_in,
                              void* d_out, int out_size) {
    const float* x = (const float*)d_in[0];
    int n = in_sizes[0];
    float* out = (float*)d_out;

    int blocks = (n + TILE - 1) / TILE;
    main_kernel<<<blocks, THREADS>>>(x, out, n);
    fix_kernel<<<2, THREADS>>>(x, out, n, blocks);

    if (out_size > n && n_in > 1) {
        cudaMemcpyAsync(out + n, d_in[1],
                        (size_t)(out_size - n) * sizeof(float),
                        cudaMemcpyDeviceToDevice);
    }
}